// round 8
// baseline (speedup 1.0000x reference)
#include <cuda_runtime.h>
#include <cstdint>

// PeakAligner: L=220, window=[57,87); start=index_max-57 in [0,29]
//   in_bounds <=> start<=28; ss=min(start,28)
//   valid <=> p[57]==max(p[0..191]) && max(p[0..56]) < that max && in_bounds
//             where p = row + ss
//   outputs: out[row][i] = valid ? p[3i] : 0 (i=0..63); mask[row] = !valid
//
// Register-resident design: only bytes [ss, ss+192) of each row are ever
// fetched (768 of 880 B). Warp-per-row; no shared memory, no barriers.

#define L_DIM 220
#define WIN_LEN 30
#define WIN_LO 57
#define MAX_START 28
#define ROWS_PER_BLOCK 8
#define THREADS 256

__device__ __forceinline__ unsigned ford(float f) {
    unsigned u = __float_as_uint(f);
    return u ^ (unsigned)(((int)u >> 31) | 0x80000000);
}
__device__ __forceinline__ float unford(unsigned t) {
    unsigned u = (t & 0x80000000u) ? (t ^ 0x80000000u) : ~t;
    return __uint_as_float(u);
}

__global__ __launch_bounds__(THREADS, 8)
void peak_aligner_kernel(const float* __restrict__ in,
                         float* __restrict__ out,
                         float* __restrict__ mask_out,
                         int K) {
    const int w    = threadIdx.x >> 5;
    const int lane = threadIdx.x & 31;
    const int row  = blockIdx.x * ROWS_PER_BLOCK + w;
    if (row >= K) return;

    const float* rp = in + (size_t)row * L_DIM;

    // ---- Pass 1: 30-float window load -> first-argmax index ----
    unsigned wu = 0u;
    if (lane < WIN_LEN) wu = ford(__ldg(rp + WIN_LO + lane));
    const unsigned wmax = __reduce_max_sync(0xffffffffu, wu);
    const unsigned wb   = __ballot_sync(0xffffffffu, wu == wmax);
    const int start = __ffs(wb) - 1;
    const bool in_bounds = (start <= MAX_START);
    const int ss = min(start, MAX_START);

    // ---- Pass 2: 192-float aligned window into 6 regs/lane ----
    const float* p = rp + ss;
    const float x0 = __ldg(p + lane);
    const float x1 = __ldg(p + lane + 32);
    const float x2 = __ldg(p + lane + 64);
    const float x3 = __ldg(p + lane + 96);
    const float x4 = __ldg(p + lane + 128);
    const float x5 = __ldg(p + lane + 160);

    const float Ml = fmaxf(fmaxf(fmaxf(x0, x1), fmaxf(x2, x3)), fmaxf(x4, x5));
    const float Pl = (lane < 25) ? fmaxf(x0, x1) : x0;       // rel<57 coverage
    const float M  = unford(__reduce_max_sync(0xffffffffu, ford(Ml)));
    const float P  = unford(__reduce_max_sync(0xffffffffu, ford(Pl)));
    const float v57 = __shfl_sync(0xffffffffu, x1, 25);       // p[57] = x1@lane25
    const bool valid = (v57 == M) && (P < M) && in_bounds;

    // ---- Downsample from registers via shuffle (no memory re-read) ----
    // o0 = p[3*lane]      : reg j = (3*lane)>>5 in {0,1,2}, src lane s = (3*lane)&31
    // o1 = p[3*lane + 96] : reg j+3,                    same s (96 % 32 == 0)
    const int i0 = 3 * lane;
    const int s  = i0 & 31;
    const int j  = i0 >> 5;
    const float a0 = __shfl_sync(0xffffffffu, x0, s);
    const float a1 = __shfl_sync(0xffffffffu, x1, s);
    const float a2 = __shfl_sync(0xffffffffu, x2, s);
    const float b0 = __shfl_sync(0xffffffffu, x3, s);
    const float b1 = __shfl_sync(0xffffffffu, x4, s);
    const float b2 = __shfl_sync(0xffffffffu, x5, s);
    float o0 = (j == 0) ? a0 : (j == 1) ? a1 : a2;
    float o1 = (j == 0) ? b0 : (j == 1) ? b1 : b2;
    o0 = valid ? o0 : 0.0f;
    o1 = valid ? o1 : 0.0f;

    float* orow = out + (size_t)row * 64;
    __stcs(orow + lane,      o0);
    __stcs(orow + lane + 32, o1);
    if (lane == 0)
        __stcs(mask_out + row, valid ? 0.0f : 1.0f);          // removed_mask = !valid
}

extern "C" void kernel_launch(void* const* d_in, const int* in_sizes, int n_in,
                              void* d_out, int out_size) {
    const float* in = (const float*)d_in[0];
    const int K = in_sizes[0] / L_DIM;
    float* out  = (float*)d_out;
    float* mask = out + (size_t)K * 64;
    const int blocks = (K + ROWS_PER_BLOCK - 1) / ROWS_PER_BLOCK;
    peak_aligner_kernel<<<blocks, THREADS>>>(in, out, mask, K);
}

// round 9
// speedup vs baseline: 1.2153x; 1.2153x over previous
#include <cuda_runtime.h>
#include <cstdint>

// PeakAligner: L=220, window=[57,87); start=index_max-57 in [0,29]
//   in_bounds <=> start<=28; ss=min(start,28)
//   valid <=> p[57]==max(p[0..191]) && max(p[0..56]) < that max && in_bounds,  p=row+ss
//   out[row][i] = valid ? p[3i] : 0 (i=0..63); mask[row] = !valid
//
// Batched register-resident design: 4 rows per warp. Only bytes [ss, ss+192)
// of each row are fetched. Per-warp load bursts of 4 (pass1) and 24 (pass2)
// keep MLP high despite the pass1->pass2 dependency.

#define L_DIM 220
#define WIN_LEN 30
#define WIN_LO 57
#define MAX_START 28
#define ROWS_PER_WARP 4
#define WARPS_PER_BLOCK 8
#define ROWS_PER_BLOCK (ROWS_PER_WARP * WARPS_PER_BLOCK)   // 32
#define THREADS 256

__device__ __forceinline__ unsigned ford(float f) {
    unsigned u = __float_as_uint(f);
    return u ^ (unsigned)(((int)u >> 31) | 0x80000000);
}
__device__ __forceinline__ float unford(unsigned t) {
    unsigned u = (t & 0x80000000u) ? (t ^ 0x80000000u) : ~t;
    return __uint_as_float(u);
}

__global__ __launch_bounds__(THREADS)
void peak_aligner_kernel(const float* __restrict__ in,
                         float* __restrict__ out,
                         float* __restrict__ mask_out,
                         int K) {
    const int w    = threadIdx.x >> 5;
    const int lane = threadIdx.x & 31;
    const int row0 = blockIdx.x * ROWS_PER_BLOCK + w * ROWS_PER_WARP;
    if (row0 >= K) return;
    const int nrows = min(ROWS_PER_WARP, K - row0);

    const float* rp = in + (size_t)row0 * L_DIM;

    // ---- Phase 1a: issue all pass-1 window loads (4 LDGs in flight) ----
    unsigned wu[ROWS_PER_WARP];
    #pragma unroll
    for (int j = 0; j < ROWS_PER_WARP; j++) {
        wu[j] = 0u;
        if (j < nrows && lane < WIN_LEN)
            wu[j] = ford(__ldg(rp + j * L_DIM + WIN_LO + lane));
    }

    // ---- Phase 1b: per-row first-argmax -> ss ----
    int ss[ROWS_PER_WARP];
    bool inb[ROWS_PER_WARP];
    #pragma unroll
    for (int j = 0; j < ROWS_PER_WARP; j++) {
        const unsigned wmax = __reduce_max_sync(0xffffffffu, wu[j]);
        const unsigned wb   = __ballot_sync(0xffffffffu, wu[j] == wmax);
        const int start = __ffs(wb) - 1;
        inb[j] = (start <= MAX_START);
        ss[j]  = min(start, MAX_START);
    }

    // ---- Phase 2a: issue all pass-2 loads (up to 24 LDGs in flight) ----
    float x[ROWS_PER_WARP][6];
    #pragma unroll
    for (int j = 0; j < ROWS_PER_WARP; j++) {
        const float* p = rp + j * L_DIM + ss[j];
        if (j < nrows) {
            #pragma unroll
            for (int k = 0; k < 6; k++)
                x[j][k] = __ldg(p + lane + 32 * k);
        } else {
            #pragma unroll
            for (int k = 0; k < 6; k++) x[j][k] = 0.0f;
        }
    }

    // ---- Phase 2b: per-row validity + register-shuffle downsample + store ----
    const int i0 = 3 * lane;
    const int sl = i0 & 31;       // source lane for both outputs (96 % 32 == 0)
    const int jr = i0 >> 5;       // source register index 0..2
    #pragma unroll
    for (int j = 0; j < ROWS_PER_WARP; j++) {
        if (j >= nrows) break;
        const float Ml = fmaxf(fmaxf(fmaxf(x[j][0], x[j][1]), fmaxf(x[j][2], x[j][3])),
                               fmaxf(x[j][4], x[j][5]));
        const float Pl = (lane < 25) ? fmaxf(x[j][0], x[j][1]) : x[j][0];
        const float M  = unford(__reduce_max_sync(0xffffffffu, ford(Ml)));
        const float P  = unford(__reduce_max_sync(0xffffffffu, ford(Pl)));
        const float v57 = __shfl_sync(0xffffffffu, x[j][1], 25);   // p[57]
        const bool valid = (v57 == M) && (P < M) && inb[j];

        const float a0 = __shfl_sync(0xffffffffu, x[j][0], sl);
        const float a1 = __shfl_sync(0xffffffffu, x[j][1], sl);
        const float a2 = __shfl_sync(0xffffffffu, x[j][2], sl);
        const float b0 = __shfl_sync(0xffffffffu, x[j][3], sl);
        const float b1 = __shfl_sync(0xffffffffu, x[j][4], sl);
        const float b2 = __shfl_sync(0xffffffffu, x[j][5], sl);
        float o0 = (jr == 0) ? a0 : (jr == 1) ? a1 : a2;
        float o1 = (jr == 0) ? b0 : (jr == 1) ? b1 : b2;
        o0 = valid ? o0 : 0.0f;
        o1 = valid ? o1 : 0.0f;

        float* orow = out + (size_t)(row0 + j) * 64;
        __stcs(orow + lane,      o0);
        __stcs(orow + lane + 32, o1);
        if (lane == 0)
            __stcs(mask_out + row0 + j, valid ? 0.0f : 1.0f);
    }
}

extern "C" void kernel_launch(void* const* d_in, const int* in_sizes, int n_in,
                              void* d_out, int out_size) {
    const float* in = (const float*)d_in[0];
    const int K = in_sizes[0] / L_DIM;
    float* out  = (float*)d_out;
    float* mask = out + (size_t)K * 64;
    const int blocks = (K + ROWS_PER_BLOCK - 1) / ROWS_PER_BLOCK;
    peak_aligner_kernel<<<blocks, THREADS>>>(in, out, mask, K);
}